// round 1
// baseline (speedup 1.0000x reference)
#include <cuda_runtime.h>
#include <math.h>

// Problem constants
#define BATCH 4
#define SEQ   2048
#define DMODEL 1024
#define NHEAD 16
#define DHEAD 64
#define NQKV  (3 * DMODEL)
#define MROWS (BATCH * SEQ)          // 8192

// Scratch (static device arrays; no runtime allocation)
__device__ float g_q [BATCH * NHEAD * SEQ * DHEAD];   // [B,H,S,Dh]
__device__ float g_kT[BATCH * NHEAD * DHEAD * SEQ];   // [B,H,Dh,S]  (pre-transposed K)
__device__ float g_v [BATCH * NHEAD * SEQ * DHEAD];   // [B,H,S,Dh]
__device__ float g_ao[BATCH * SEQ * DMODEL];          // [B,S,D] attention output (heads combined)

// ---------------------------------------------------------------------------
// GEMM 1: qkv = x @ w_qkv + b_qkv, scattered into g_q / g_kT / g_v
// C[8192, 3072] = X[8192,1024] @ W[1024,3072]
// 128x128x8 tile, 256 threads, 8x8 per thread.
// ---------------------------------------------------------------------------
__global__ __launch_bounds__(256) void qkv_gemm_kernel(
    const float* __restrict__ X, const float* __restrict__ W,
    const float* __restrict__ bias)
{
    const int K = DMODEL, N = NQKV;
    __shared__ float As[8][128];
    __shared__ float Bs[8][128];

    const int tid = threadIdx.x;
    const int tx = tid & 15, ty = tid >> 4;
    const int m0 = blockIdx.y * 128, n0 = blockIdx.x * 128;

    float acc[8][8];
    #pragma unroll
    for (int i = 0; i < 8; i++)
        #pragma unroll
        for (int j = 0; j < 8; j++) acc[i][j] = 0.f;

    const int a_row = tid >> 1, a_col = (tid & 1) * 4;
    const int b_row = tid >> 5, b_col = (tid & 31) * 4;
    const float* Aptr = X + (size_t)(m0 + a_row) * K + a_col;
    const float* Bptr = W + (size_t)b_row * N + n0 + b_col;

    for (int k0 = 0; k0 < K; k0 += 8) {
        float4 av = *(const float4*)(Aptr + k0);
        As[a_col + 0][a_row] = av.x;
        As[a_col + 1][a_row] = av.y;
        As[a_col + 2][a_row] = av.z;
        As[a_col + 3][a_row] = av.w;
        *(float4*)&Bs[b_row][b_col] = *(const float4*)(Bptr + (size_t)k0 * N);
        __syncthreads();

        #pragma unroll
        for (int kk = 0; kk < 8; kk++) {
            float a[8], b[8];
            *(float4*)(a)     = *(float4*)&As[kk][ty * 8];
            *(float4*)(a + 4) = *(float4*)&As[kk][ty * 8 + 4];
            *(float4*)(b)     = *(float4*)&Bs[kk][tx * 8];
            *(float4*)(b + 4) = *(float4*)&Bs[kk][tx * 8 + 4];
            #pragma unroll
            for (int i = 0; i < 8; i++)
                #pragma unroll
                for (int j = 0; j < 8; j++)
                    acc[i][j] += a[i] * b[j];
        }
        __syncthreads();
    }

    // Epilogue: scatter into head-major q / transposed k / v
    #pragma unroll
    for (int i = 0; i < 8; i++) {
        const int m  = m0 + ty * 8 + i;
        const int b_ = m >> 11;          // m / 2048
        const int s_ = m & 2047;
        #pragma unroll
        for (int j = 0; j < 8; j++) {
            const int n = n0 + tx * 8 + j;
            const float c = acc[i][j] + bias[n];
            const int sec  = n >> 10;    // 0=q 1=k 2=v
            const int dcol = n & 1023;
            const int h_ = dcol >> 6;
            const int dh = dcol & 63;
            const int bh = b_ * NHEAD + h_;
            if (sec == 0)       g_q [((size_t)bh * SEQ + s_) * DHEAD + dh] = c;
            else if (sec == 1)  g_kT[((size_t)bh * DHEAD + dh) * SEQ + s_] = c;
            else                g_v [((size_t)bh * SEQ + s_) * DHEAD + dh] = c;
        }
    }
}

// ---------------------------------------------------------------------------
// Flash attention: one CTA = one 64-row Q tile of one (b,h).
// 256 threads as 16x16; each thread owns a 4x4 tile of the 64x64 S/O blocks.
// Online softmax; P staged through smem for the P@V micro-GEMM.
// Dynamic smem: Qs(16KB) + Kts(16KB) + Vs(16KB) + Ps(16KB) = 64KB.
// ---------------------------------------------------------------------------
__global__ __launch_bounds__(256) void attn_kernel()
{
    extern __shared__ float sm[];
    float* Qs  = sm;              // [64][64]  (pre-scaled by 1/8)
    float* Kts = sm + 4096;       // [d][s] 64x64
    float* Vs  = sm + 8192;       // [s][d] 64x64
    float* Ps  = sm + 12288;      // [64][64]

    const int bh = blockIdx.y;
    const int q0 = blockIdx.x * 64;
    const int tid = threadIdx.x;
    const int tx = tid & 15, ty = tid >> 4;

    const float* qg  = g_q  + (size_t)bh * SEQ * DHEAD + (size_t)q0 * DHEAD;
    const float* ktg = g_kT + (size_t)bh * DHEAD * SEQ;
    const float* vg  = g_v  + (size_t)bh * SEQ * DHEAD;

    // Load Q tile (contiguous 4096 floats), fold in softmax scale 1/sqrt(64)
    for (int c = tid; c < 1024; c += 256) {
        float4 v = ((const float4*)qg)[c];
        v.x *= 0.125f; v.y *= 0.125f; v.z *= 0.125f; v.w *= 0.125f;
        ((float4*)Qs)[c] = v;
    }

    float acc[4][4];
    float mrow[4], lrow[4];
    #pragma unroll
    for (int i = 0; i < 4; i++) {
        mrow[i] = -INFINITY; lrow[i] = 0.f;
        #pragma unroll
        for (int j = 0; j < 4; j++) acc[i][j] = 0.f;
    }

    for (int kt = 0; kt < 32; kt++) {
        const int kc0 = kt * 64;
        __syncthreads();  // prev iter's P@V (Vs) done; first iter: Qs ready

        // Kt tile: rows d, 64 contiguous floats each (coalesced, conflict-free)
        for (int c = tid; c < 1024; c += 256) {
            const int d = c >> 4, s4 = c & 15;
            ((float4*)(Kts + d * 64))[s4] =
                *(const float4*)(ktg + (size_t)d * SEQ + kc0 + s4 * 4);
        }
        // V tile: contiguous
        for (int c = tid; c < 1024; c += 256)
            ((float4*)Vs)[c] = ((const float4*)(vg + (size_t)kc0 * DHEAD))[c];
        __syncthreads();

        // S = Qs @ Kts  (S[i][j], rows ty*4+i, cols tx*4+j)
        float sv[4][4];
        #pragma unroll
        for (int i = 0; i < 4; i++)
            #pragma unroll
            for (int j = 0; j < 4; j++) sv[i][j] = 0.f;

        #pragma unroll
        for (int d = 0; d < 64; d += 4) {
            float qa[4][4], ka[4][4];
            #pragma unroll
            for (int i = 0; i < 4; i++) {
                float4 t = *(const float4*)&Qs[(ty * 4 + i) * 64 + d];
                qa[i][0] = t.x; qa[i][1] = t.y; qa[i][2] = t.z; qa[i][3] = t.w;
            }
            #pragma unroll
            for (int r = 0; r < 4; r++) {
                float4 t = *(const float4*)&Kts[(d + r) * 64 + tx * 4];
                ka[r][0] = t.x; ka[r][1] = t.y; ka[r][2] = t.z; ka[r][3] = t.w;
            }
            #pragma unroll
            for (int i = 0; i < 4; i++)
                #pragma unroll
                for (int j = 0; j < 4; j++)
                    sv[i][j] += qa[i][0] * ka[0][j] + qa[i][1] * ka[1][j]
                              + qa[i][2] * ka[2][j] + qa[i][3] * ka[3][j];
        }

        // Online softmax (row reductions across the 16 tx lanes of a half-warp)
        #pragma unroll
        for (int i = 0; i < 4; i++) {
            float rm = fmaxf(fmaxf(sv[i][0], sv[i][1]), fmaxf(sv[i][2], sv[i][3]));
            #pragma unroll
            for (int o = 1; o < 16; o <<= 1)
                rm = fmaxf(rm, __shfl_xor_sync(0xffffffffu, rm, o));
            const float nmax = fmaxf(mrow[i], rm);
            const float f = __expf(mrow[i] - nmax);
            float rs = 0.f;
            #pragma unroll
            for (int j = 0; j < 4; j++) {
                sv[i][j] = __expf(sv[i][j] - nmax);
                rs += sv[i][j];
            }
            #pragma unroll
            for (int o = 1; o < 16; o <<= 1)
                rs += __shfl_xor_sync(0xffffffffu, rs, o);
            lrow[i] = lrow[i] * f + rs;
            mrow[i] = nmax;
            #pragma unroll
            for (int j = 0; j < 4; j++) acc[i][j] *= f;
        }

        // Stage P to smem
        #pragma unroll
        for (int i = 0; i < 4; i++)
            *(float4*)&Ps[(ty * 4 + i) * 64 + tx * 4] =
                make_float4(sv[i][0], sv[i][1], sv[i][2], sv[i][3]);
        __syncthreads();

        // O += P @ V
        #pragma unroll
        for (int k = 0; k < 64; k += 4) {
            float pa[4][4], va[4][4];
            #pragma unroll
            for (int i = 0; i < 4; i++) {
                float4 t = *(const float4*)&Ps[(ty * 4 + i) * 64 + k];
                pa[i][0] = t.x; pa[i][1] = t.y; pa[i][2] = t.z; pa[i][3] = t.w;
            }
            #pragma unroll
            for (int r = 0; r < 4; r++) {
                float4 t = *(const float4*)&Vs[(k + r) * 64 + tx * 4];
                va[r][0] = t.x; va[r][1] = t.y; va[r][2] = t.z; va[r][3] = t.w;
            }
            #pragma unroll
            for (int i = 0; i < 4; i++)
                #pragma unroll
                for (int j = 0; j < 4; j++)
                    acc[i][j] += pa[i][0] * va[0][j] + pa[i][1] * va[1][j]
                               + pa[i][2] * va[2][j] + pa[i][3] * va[3][j];
        }
    }

    // Normalize and write combined-heads output [B,S,D]
    const int h_ = bh & (NHEAD - 1);
    const int b_ = bh >> 4;
    #pragma unroll
    for (int i = 0; i < 4; i++) {
        const int s_ = q0 + ty * 4 + i;
        const float inv = 1.0f / lrow[i];
        float4 o = make_float4(acc[i][0] * inv, acc[i][1] * inv,
                               acc[i][2] * inv, acc[i][3] * inv);
        *(float4*)&g_ao[((size_t)(b_ * SEQ + s_)) * DMODEL + h_ * DHEAD + tx * 4] = o;
    }
}

// ---------------------------------------------------------------------------
// GEMM 2: out = g_ao @ w_out + b_out   (8192x1024x1024) -> d_out
// ---------------------------------------------------------------------------
__global__ __launch_bounds__(256) void out_gemm_kernel(
    const float* __restrict__ W, const float* __restrict__ bias,
    float* __restrict__ Cout)
{
    const int K = DMODEL, N = DMODEL;
    const float* X = g_ao;
    __shared__ float As[8][128];
    __shared__ float Bs[8][128];

    const int tid = threadIdx.x;
    const int tx = tid & 15, ty = tid >> 4;
    const int m0 = blockIdx.y * 128, n0 = blockIdx.x * 128;

    float acc[8][8];
    #pragma unroll
    for (int i = 0; i < 8; i++)
        #pragma unroll
        for (int j = 0; j < 8; j++) acc[i][j] = 0.f;

    const int a_row = tid >> 1, a_col = (tid & 1) * 4;
    const int b_row = tid >> 5, b_col = (tid & 31) * 4;
    const float* Aptr = X + (size_t)(m0 + a_row) * K + a_col;
    const float* Bptr = W + (size_t)b_row * N + n0 + b_col;

    for (int k0 = 0; k0 < K; k0 += 8) {
        float4 av = *(const float4*)(Aptr + k0);
        As[a_col + 0][a_row] = av.x;
        As[a_col + 1][a_row] = av.y;
        As[a_col + 2][a_row] = av.z;
        As[a_col + 3][a_row] = av.w;
        *(float4*)&Bs[b_row][b_col] = *(const float4*)(Bptr + (size_t)k0 * N);
        __syncthreads();

        #pragma unroll
        for (int kk = 0; kk < 8; kk++) {
            float a[8], b[8];
            *(float4*)(a)     = *(float4*)&As[kk][ty * 8];
            *(float4*)(a + 4) = *(float4*)&As[kk][ty * 8 + 4];
            *(float4*)(b)     = *(float4*)&Bs[kk][tx * 8];
            *(float4*)(b + 4) = *(float4*)&Bs[kk][tx * 8 + 4];
            #pragma unroll
            for (int i = 0; i < 8; i++)
                #pragma unroll
                for (int j = 0; j < 8; j++)
                    acc[i][j] += a[i] * b[j];
        }
        __syncthreads();
    }

    #pragma unroll
    for (int i = 0; i < 8; i++) {
        const int m = m0 + ty * 8 + i;
        float* crow = Cout + (size_t)m * N + n0 + tx * 8;
        #pragma unroll
        for (int j4 = 0; j4 < 8; j4 += 4) {
            const int n = n0 + tx * 8 + j4;
            float4 o = make_float4(acc[i][j4 + 0] + bias[n + 0],
                                   acc[i][j4 + 1] + bias[n + 1],
                                   acc[i][j4 + 2] + bias[n + 2],
                                   acc[i][j4 + 3] + bias[n + 3]);
            *(float4*)(crow + j4) = o;
        }
    }
}

// ---------------------------------------------------------------------------
extern "C" void kernel_launch(void* const* d_in, const int* in_sizes, int n_in,
                              void* d_out, int out_size)
{
    const float* x     = (const float*)d_in[0];
    const float* w_qkv = (const float*)d_in[1];
    const float* b_qkv = (const float*)d_in[2];
    const float* w_out = (const float*)d_in[3];
    const float* b_out = (const float*)d_in[4];
    float* out = (float*)d_out;

    // 64KB dynamic smem for the attention kernel
    cudaFuncSetAttribute(attn_kernel,
                         cudaFuncAttributeMaxDynamicSharedMemorySize, 65536);

    dim3 g1(NQKV / 128, MROWS / 128);       // 24 x 64
    qkv_gemm_kernel<<<g1, 256>>>(x, w_qkv, b_qkv);

    dim3 g2(SEQ / 64, BATCH * NHEAD);       // 32 x 64
    attn_kernel<<<g2, 256, 65536>>>();

    dim3 g3(DMODEL / 128, MROWS / 128);     // 8 x 64
    out_gemm_kernel<<<g3, 256>>>(w_out, b_out, out);
}

// round 5
// speedup vs baseline: 3.2276x; 3.2276x over previous
#include <cuda_runtime.h>
#include <math.h>
#include <cstdint>

// Problem constants
#define BATCH 4
#define SEQ   2048
#define DMODEL 1024
#define NHEAD 16
#define DHEAD 64
#define NQKV  (3 * DMODEL)
#define MROWS (BATCH * SEQ)          // 8192

// ---------------------------------------------------------------------------
// Scratch (static device arrays; referenced ONLY from device code)
// ---------------------------------------------------------------------------
__device__ float g_q [BATCH * NHEAD * SEQ * DHEAD];   // [B,H,S,Dh] (scaled, tf32-rounded)
__device__ float g_k [BATCH * NHEAD * SEQ * DHEAD];   // [B,H,S,Dh] (tf32-rounded)
__device__ float g_v [BATCH * NHEAD * SEQ * DHEAD];   // [B,H,S,Dh] (tf32-rounded)
__device__ float g_ao[BATCH * SEQ * DMODEL];          // [B,S,D]   (tf32-rounded)
__device__ float g_xr   [MROWS * DMODEL];             // tf32-rounded x
__device__ float g_wqkvr[DMODEL * NQKV];              // tf32-rounded w_qkv
__device__ float g_woutr[DMODEL * DMODEL];            // tf32-rounded w_out

// ---------------------------------------------------------------------------
// Helpers (base sm_103 ISA only: mma.sync + cp.async)
// ---------------------------------------------------------------------------
__device__ __forceinline__ uint32_t smem_u32(const void* p) {
    uint32_t a;
    asm("{ .reg .u64 t; cvta.to.shared.u64 t, %1; cvt.u32.u64 %0, t; }"
        : "=r"(a) : "l"(p));
    return a;
}

__device__ __forceinline__ void cp_async16(uint32_t dst, const void* src) {
    asm volatile("cp.async.ca.shared.global [%0], [%1], 16;\n"
                 :: "r"(dst), "l"(src));
}
#define CP_COMMIT() asm volatile("cp.async.commit_group;\n" ::: "memory")
#define CP_WAIT(n)  asm volatile("cp.async.wait_group %0;\n" :: "n"(n) : "memory")

__device__ __forceinline__ float tf32r(float x) {
    uint32_t u;
    asm("cvt.rna.tf32.f32 %0, %1;" : "=r"(u) : "f"(x));
    return __uint_as_float(u);
}

__device__ __forceinline__ float ex2(float x) {
    float y;
    asm("ex2.approx.ftz.f32 %0, %1;" : "=f"(y) : "f"(x));
    return y;
}

// D(f32) += A(tf32) * B(tf32), m16n8k8
__device__ __forceinline__ void mma_tf32(float* d,
                                         uint32_t a0, uint32_t a1,
                                         uint32_t a2, uint32_t a3,
                                         uint32_t b0, uint32_t b1) {
    asm volatile(
        "mma.sync.aligned.m16n8k8.row.col.f32.tf32.tf32.f32 "
        "{%0,%1,%2,%3}, {%4,%5,%6,%7}, {%8,%9}, {%0,%1,%2,%3};\n"
        : "+f"(d[0]), "+f"(d[1]), "+f"(d[2]), "+f"(d[3])
        : "r"(a0), "r"(a1), "r"(a2), "r"(a3), "r"(b0), "r"(b1));
}

// ---------------------------------------------------------------------------
// Elementwise tf32 rounding. which: 0 -> g_xr, 1 -> g_wqkvr, 2 -> g_woutr
// ---------------------------------------------------------------------------
__global__ void round_tf32_kernel(const float* __restrict__ in, int n4, int which)
{
    float* out = (which == 0) ? g_xr : (which == 1) ? g_wqkvr : g_woutr;
    int i = blockIdx.x * blockDim.x + threadIdx.x;
    if (i < n4) {
        float4 v = ((const float4*)in)[i];
        v.x = tf32r(v.x); v.y = tf32r(v.y);
        v.z = tf32r(v.z); v.w = tf32r(v.w);
        ((float4*)out)[i] = v;
    }
}

// ---------------------------------------------------------------------------
// tf32 mma.sync GEMM:  C[M,N] = X[M,1024] @ W[1024,N] (+bias)
// CTA tile 128x128, BK=32, 256 threads = 8 warps (2m x 4n), warp tile 64x32.
// Double-buffered smem via cp.async.
// mode 0: X=g_xr, W=g_wqkvr, scatter epilogue into g_q(*0.125)/g_k/g_v (tf32r)
// mode 1: X=g_ao, W=g_woutr, plain epilogue (+bias) into Cout
// ---------------------------------------------------------------------------
#define GS_XSTRIDE 36            // floats per A-row (32 + 4 pad)
#define GS_WSTRIDE 132           // floats per B-row (128 + 4 pad)
#define GS_XSTAGE  (128 * GS_XSTRIDE)   // 4608 floats
#define GS_WSTAGE  (32 * GS_WSTRIDE)    // 4224 floats
#define GS_WBASE   (2 * GS_XSTAGE)      // 9216 floats
#define GEMM_SMEM  ((2 * GS_XSTAGE + 2 * GS_WSTAGE) * 4)   // 70656 B

__global__ __launch_bounds__(256) void mma_gemm_kernel(
    const float* __restrict__ bias, float* __restrict__ Cout,
    int N, int mode)
{
    extern __shared__ float sm[];
    const uint32_t sb = smem_u32(sm);
    const int tid = threadIdx.x, lane = tid & 31, w = tid >> 5;
    const int m0 = blockIdx.y * 128, n0 = blockIdx.x * 128;
    const int wm = (w >> 2) * 64, wn = (w & 3) * 32;
    const int q = lane & 3, r = lane >> 2;

    const float* X = (mode == 0) ? g_xr : g_ao;
    const float* W = (mode == 0) ? g_wqkvr : g_woutr;

    float c[4][4][4];
    #pragma unroll
    for (int mt = 0; mt < 4; mt++)
        #pragma unroll
        for (int nt = 0; nt < 4; nt++)
            #pragma unroll
            for (int k = 0; k < 4; k++) c[mt][nt][k] = 0.f;

    auto load_stage = [&](int s, int kt) {
        const int k0 = kt * 32;
        const uint32_t xb = sb + (uint32_t)(s * GS_XSTAGE) * 4;
        const uint32_t wb = sb + (uint32_t)(GS_WBASE + s * GS_WSTAGE) * 4;
        #pragma unroll
        for (int i = 0; i < 4; i++) {
            const int idx = tid + i * 256;
            const int row = idx >> 3, kc = (idx & 7) * 4;
            cp_async16(xb + (uint32_t)(row * GS_XSTRIDE + kc) * 4,
                       X + (size_t)(m0 + row) * DMODEL + k0 + kc);
        }
        #pragma unroll
        for (int i = 0; i < 4; i++) {
            const int idx = tid + i * 256;
            const int row = idx >> 5, nc = (idx & 31) * 4;
            cp_async16(wb + (uint32_t)(row * GS_WSTRIDE + nc) * 4,
                       W + (size_t)(k0 + row) * N + n0 + nc);
        }
    };

    load_stage(0, 0);
    CP_COMMIT();

    const int NT = DMODEL / 32;   // 32 k-stages
    for (int kt = 0; kt < NT; kt++) {
        if (kt + 1 < NT) { load_stage((kt + 1) & 1, kt + 1); CP_COMMIT(); }
        if (kt + 1 < NT) CP_WAIT(1); else CP_WAIT(0);
        __syncthreads();

        const float* xs = sm + (kt & 1) * GS_XSTAGE;
        const float* ws = sm + GS_WBASE + (kt & 1) * GS_WSTAGE;

        #pragma unroll
        for (int ks = 0; ks < 4; ks++) {
            uint32_t a[4][4];
            #pragma unroll
            for (int mt = 0; mt < 4; mt++) {
                const int row = wm + mt * 16 + r;
                a[mt][0] = __float_as_uint(xs[row * GS_XSTRIDE + ks * 8 + q]);
                a[mt][1] = __float_as_uint(xs[(row + 8) * GS_XSTRIDE + ks * 8 + q]);
                a[mt][2] = __float_as_uint(xs[row * GS_XSTRIDE + ks * 8 + q + 4]);
                a[mt][3] = __float_as_uint(xs[(row + 8) * GS_XSTRIDE + ks * 8 + q + 4]);
            }
            #pragma unroll
            for (int nt = 0; nt < 4; nt++) {
                const int col = wn + nt * 8 + r;
                const uint32_t b0 = __float_as_uint(ws[(ks * 8 + q) * GS_WSTRIDE + col]);
                const uint32_t b1 = __float_as_uint(ws[(ks * 8 + q + 4) * GS_WSTRIDE + col]);
                #pragma unroll
                for (int mt = 0; mt < 4; mt++)
                    mma_tf32(c[mt][nt], a[mt][0], a[mt][1], a[mt][2], a[mt][3], b0, b1);
            }
        }
        __syncthreads();
    }

    // Epilogue
    #pragma unroll
    for (int mt = 0; mt < 4; mt++) {
        #pragma unroll
        for (int half = 0; half < 2; half++) {
            const int m = m0 + wm + mt * 16 + r + half * 8;
            #pragma unroll
            for (int nt = 0; nt < 4; nt++) {
                const int n = n0 + wn + nt * 8 + 2 * q;
                float v0 = c[mt][nt][half * 2 + 0] + bias[n];
                float v1 = c[mt][nt][half * 2 + 1] + bias[n + 1];
                if (mode == 0) {
                    const int sec = n >> 10, dcol = n & 1023;
                    const int h = dcol >> 6, dh = dcol & 63;
                    const int b_ = m >> 11, s_ = m & 2047;
                    float* dst;
                    if (sec == 0) { v0 *= 0.125f; v1 *= 0.125f; dst = g_q; }
                    else dst = (sec == 1) ? g_k : g_v;
                    const int bh = b_ * NHEAD + h;
                    *(float2*)&dst[((size_t)bh * SEQ + s_) * DHEAD + dh] =
                        make_float2(tf32r(v0), tf32r(v1));
                } else {
                    *(float2*)&Cout[(size_t)m * DMODEL + n] = make_float2(v0, v1);
                }
            }
        }
    }
}

// ---------------------------------------------------------------------------
// Flash attention on tf32 mma.sync.
// CTA = 64 Q rows of one (b,h); 128 threads = 4 warps; warp w owns rows
// [w*16, w*16+16). Per key-tile (64 keys): S = Q@K^T (mma), fragment-level
// online softmax in exp2 domain, P staged per-warp through smem, O += P@V (mma).
// K/V double-buffered via cp.async.
// smem floats: Qs[64][68] @0 | Ks[2][64][68] @4352 | Vs[2][64][68] @13056
//              | Ps[64][68] @21760   (total 26112 floats = 104448 B)
// ---------------------------------------------------------------------------
#define AS_STRIDE 68
#define AS_TILE   (64 * AS_STRIDE)   // 4352 floats
#define AS_KBASE  AS_TILE            // 4352
#define AS_VBASE  (3 * AS_TILE)      // 13056
#define AS_PBASE  (5 * AS_TILE)      // 21760
#define ATTN_SMEM (6 * AS_TILE * 4)  // 104448 B

__global__ __launch_bounds__(128) void attn_mma_kernel()
{
    extern __shared__ float sm[];
    const uint32_t sb = smem_u32(sm);
    const int bh = blockIdx.y, q0 = blockIdx.x * 64;
    const int tid = threadIdx.x, lane = tid & 31, w = tid >> 5;
    const int q = lane & 3, r = lane >> 2;

    const float* qg = g_q + ((size_t)bh * SEQ + q0) * DHEAD;
    const float* kg = g_k + (size_t)bh * SEQ * DHEAD;
    const float* vg = g_v + (size_t)bh * SEQ * DHEAD;

    auto load_kv = [&](int s, int kc0) {
        #pragma unroll
        for (int i = 0; i < 8; i++) {
            const int idx = tid + i * 128;
            const int row = idx >> 4, c4 = (idx & 15) * 4;
            cp_async16(sb + (uint32_t)(AS_KBASE + s * AS_TILE + row * AS_STRIDE + c4) * 4,
                       kg + (size_t)(kc0 + row) * DHEAD + c4);
            cp_async16(sb + (uint32_t)(AS_VBASE + s * AS_TILE + row * AS_STRIDE + c4) * 4,
                       vg + (size_t)(kc0 + row) * DHEAD + c4);
        }
    };

    load_kv(0, 0);
    CP_COMMIT();

    // Q tile (already scaled by 1/8 and tf32-rounded at QKV epilogue)
    #pragma unroll
    for (int i = 0; i < 8; i++) {
        const int idx = tid + i * 128;
        const int row = idx >> 4, c4 = (idx & 15) * 4;
        *(float4*)&sm[row * AS_STRIDE + c4] = *(const float4*)(qg + (size_t)row * DHEAD + c4);
    }

    float mx[2] = {-INFINITY, -INFINITY};
    float l[2]  = {0.f, 0.f};
    float oacc[8][4];
    #pragma unroll
    for (int nt = 0; nt < 8; nt++)
        #pragma unroll
        for (int k = 0; k < 4; k++) oacc[nt][k] = 0.f;

    const float* Ps = sm + AS_PBASE;
    const int prow0 = w * 16 + r;

    for (int kt = 0; kt < 32; kt++) {
        const int buf = kt & 1;
        if (kt + 1 < 32) { load_kv((kt + 1) & 1, (kt + 1) * 64); CP_COMMIT(); }
        if (kt + 1 < 32) CP_WAIT(1); else CP_WAIT(0);
        __syncthreads();

        const float* ks = sm + AS_KBASE + buf * AS_TILE;
        const float* vs = sm + AS_VBASE + buf * AS_TILE;

        // S = Q @ K^T  (warp: 16 rows x 64 keys)
        float sacc[8][4];
        #pragma unroll
        for (int nt = 0; nt < 8; nt++)
            #pragma unroll
            for (int k = 0; k < 4; k++) sacc[nt][k] = 0.f;

        #pragma unroll
        for (int ksi = 0; ksi < 8; ksi++) {
            const uint32_t a0 = __float_as_uint(sm[prow0 * AS_STRIDE + ksi * 8 + q]);
            const uint32_t a1 = __float_as_uint(sm[(prow0 + 8) * AS_STRIDE + ksi * 8 + q]);
            const uint32_t a2 = __float_as_uint(sm[prow0 * AS_STRIDE + ksi * 8 + q + 4]);
            const uint32_t a3 = __float_as_uint(sm[(prow0 + 8) * AS_STRIDE + ksi * 8 + q + 4]);
            #pragma unroll
            for (int nt = 0; nt < 8; nt++) {
                const uint32_t b0 = __float_as_uint(ks[(nt * 8 + r) * AS_STRIDE + ksi * 8 + q]);
                const uint32_t b1 = __float_as_uint(ks[(nt * 8 + r) * AS_STRIDE + ksi * 8 + q + 4]);
                mma_tf32(sacc[nt], a0, a1, a2, a3, b0, b1);
            }
        }

        // Online softmax in exp2 domain (Q pre-scaled, so logit = S)
        const float L2E = 1.4426950408889634f;
        float tmax0 = -INFINITY, tmax1 = -INFINITY;
        #pragma unroll
        for (int nt = 0; nt < 8; nt++) {
            #pragma unroll
            for (int k = 0; k < 4; k++) sacc[nt][k] *= L2E;
            tmax0 = fmaxf(tmax0, fmaxf(sacc[nt][0], sacc[nt][1]));
            tmax1 = fmaxf(tmax1, fmaxf(sacc[nt][2], sacc[nt][3]));
        }
        #pragma unroll
        for (int o = 1; o < 4; o <<= 1) {
            tmax0 = fmaxf(tmax0, __shfl_xor_sync(0xffffffffu, tmax0, o));
            tmax1 = fmaxf(tmax1, __shfl_xor_sync(0xffffffffu, tmax1, o));
        }
        const float mn0 = fmaxf(mx[0], tmax0), mn1 = fmaxf(mx[1], tmax1);
        const float f0 = ex2(mx[0] - mn0),     f1 = ex2(mx[1] - mn1);
        float rs0 = 0.f, rs1 = 0.f;
        #pragma unroll
        for (int nt = 0; nt < 8; nt++) {
            sacc[nt][0] = ex2(sacc[nt][0] - mn0);
            sacc[nt][1] = ex2(sacc[nt][1] - mn0);
            sacc[nt][2] = ex2(sacc[nt][2] - mn1);
            sacc[nt][3] = ex2(sacc[nt][3] - mn1);
            rs0 += sacc[nt][0] + sacc[nt][1];
            rs1 += sacc[nt][2] + sacc[nt][3];
        }
        #pragma unroll
        for (int o = 1; o < 4; o <<= 1) {
            rs0 += __shfl_xor_sync(0xffffffffu, rs0, o);
            rs1 += __shfl_xor_sync(0xffffffffu, rs1, o);
        }
        l[0] = l[0] * f0 + rs0;  l[1] = l[1] * f1 + rs1;
        mx[0] = mn0;             mx[1] = mn1;

        // Rescale O, stage P (per-warp-private rows: __syncwarp is sufficient)
        #pragma unroll
        for (int nt = 0; nt < 8; nt++) {
            oacc[nt][0] *= f0; oacc[nt][1] *= f0;
            oacc[nt][2] *= f1; oacc[nt][3] *= f1;
            *(float2*)((float*)Ps + prow0 * AS_STRIDE + nt * 8 + 2 * q) =
                make_float2(tf32r(sacc[nt][0]), tf32r(sacc[nt][1]));
            *(float2*)((float*)Ps + (prow0 + 8) * AS_STRIDE + nt * 8 + 2 * q) =
                make_float2(tf32r(sacc[nt][2]), tf32r(sacc[nt][3]));
        }
        __syncwarp();

        // O += P @ V
        #pragma unroll
        for (int ksi = 0; ksi < 8; ksi++) {
            const uint32_t a0 = __float_as_uint(Ps[prow0 * AS_STRIDE + ksi * 8 + q]);
            const uint32_t a1 = __float_as_uint(Ps[(prow0 + 8) * AS_STRIDE + ksi * 8 + q]);
            const uint32_t a2 = __float_as_uint(Ps[prow0 * AS_STRIDE + ksi * 8 + q + 4]);
            const uint32_t a3 = __float_as_uint(Ps[(prow0 + 8) * AS_STRIDE + ksi * 8 + q + 4]);
            #pragma unroll
            for (int nt = 0; nt < 8; nt++) {
                const uint32_t b0 = __float_as_uint(vs[(ksi * 8 + q) * AS_STRIDE + nt * 8 + r]);
                const uint32_t b1 = __float_as_uint(vs[(ksi * 8 + q + 4) * AS_STRIDE + nt * 8 + r]);
                mma_tf32(oacc[nt], a0, a1, a2, a3, b0, b1);
            }
        }
        __syncthreads();   // all reads of Ks/Vs[buf] done before next prefetch overwrites
    }

    // Epilogue: normalize, round to tf32 (g_ao feeds the out-proj mma GEMM)
    const float inv0 = 1.f / l[0], inv1 = 1.f / l[1];
    const int b_ = bh >> 4, h = bh & (NHEAD - 1);
    const size_t base0 = ((size_t)(b_ * SEQ + q0 + w * 16 + r)) * DMODEL + h * DHEAD;
    const size_t base1 = base0 + (size_t)8 * DMODEL;
    #pragma unroll
    for (int nt = 0; nt < 8; nt++) {
        *(float2*)&g_ao[base0 + nt * 8 + 2 * q] =
            make_float2(tf32r(oacc[nt][0] * inv0), tf32r(oacc[nt][1] * inv0));
        *(float2*)&g_ao[base1 + nt * 8 + 2 * q] =
            make_float2(tf32r(oacc[nt][2] * inv1), tf32r(oacc[nt][3] * inv1));
    }
}

// ---------------------------------------------------------------------------
extern "C" void kernel_launch(void* const* d_in, const int* in_sizes, int n_in,
                              void* d_out, int out_size)
{
    const float* x     = (const float*)d_in[0];
    const float* w_qkv = (const float*)d_in[1];
    const float* b_qkv = (const float*)d_in[2];
    const float* w_out = (const float*)d_in[3];
    const float* b_out = (const float*)d_in[4];
    float* out = (float*)d_out;

    cudaFuncSetAttribute(mma_gemm_kernel,
                         cudaFuncAttributeMaxDynamicSharedMemorySize, GEMM_SMEM);
    cudaFuncSetAttribute(attn_mma_kernel,
                         cudaFuncAttributeMaxDynamicSharedMemorySize, ATTN_SMEM);

    // Round inputs to tf32 (destinations selected inside the kernel)
    round_tf32_kernel<<<(MROWS * DMODEL / 4 + 255) / 256, 256>>>(x, MROWS * DMODEL / 4, 0);
    round_tf32_kernel<<<(DMODEL * NQKV / 4 + 255) / 256, 256>>>(w_qkv, DMODEL * NQKV / 4, 1);
    round_tf32_kernel<<<(DMODEL * DMODEL / 4 + 255) / 256, 256>>>(w_out, DMODEL * DMODEL / 4, 2);

    // QKV projection
    dim3 g1(NQKV / 128, MROWS / 128);   // 24 x 64
    mma_gemm_kernel<<<g1, 256, GEMM_SMEM>>>(b_qkv, nullptr, NQKV, 0);

    // Attention
    dim3 g2(SEQ / 64, BATCH * NHEAD);   // 32 x 64
    attn_mma_kernel<<<g2, 128, ATTN_SMEM>>>();

    // Output projection
    dim3 g3(DMODEL / 128, MROWS / 128); // 8 x 64
    mma_gemm_kernel<<<g3, 256, GEMM_SMEM>>>(b_out, out, DMODEL, 1);
}

// round 6
// speedup vs baseline: 3.9757x; 1.2318x over previous
#include <cuda_runtime.h>
#include <math.h>
#include <cstdint>

// Problem constants
#define BATCH 4
#define SEQ   2048
#define DMODEL 1024
#define NHEAD 16
#define DHEAD 64
#define NQKV  (3 * DMODEL)
#define MROWS (BATCH * SEQ)          // 8192

// ---------------------------------------------------------------------------
// Scratch (static device arrays; referenced ONLY from device code)
// ---------------------------------------------------------------------------
__device__ float g_q [BATCH * NHEAD * SEQ * DHEAD];   // [B,H,S,Dh] (scaled, tf32-rounded)
__device__ float g_k [BATCH * NHEAD * SEQ * DHEAD];   // [B,H,S,Dh] (tf32-rounded)
__device__ float g_v [BATCH * NHEAD * SEQ * DHEAD];   // [B,H,S,Dh] (tf32-rounded)
__device__ float g_ao[BATCH * SEQ * DMODEL];          // [B,S,D]   (tf32-rounded)
__device__ float g_xr   [MROWS * DMODEL];             // tf32-rounded x
__device__ float g_wqkvr[DMODEL * NQKV];              // tf32-rounded w_qkv
__device__ float g_woutr[DMODEL * DMODEL];            // tf32-rounded w_out

// ---------------------------------------------------------------------------
// Helpers (base sm_103 ISA only: mma.sync + cp.async)
// ---------------------------------------------------------------------------
__device__ __forceinline__ uint32_t smem_u32(const void* p) {
    uint32_t a;
    asm("{ .reg .u64 t; cvta.to.shared.u64 t, %1; cvt.u32.u64 %0, t; }"
        : "=r"(a) : "l"(p));
    return a;
}

__device__ __forceinline__ void cp_async16(uint32_t dst, const void* src) {
    asm volatile("cp.async.ca.shared.global [%0], [%1], 16;\n"
                 :: "r"(dst), "l"(src));
}
#define CP_COMMIT() asm volatile("cp.async.commit_group;\n" ::: "memory")
#define CP_WAIT(n)  asm volatile("cp.async.wait_group %0;\n" :: "n"(n) : "memory")

__device__ __forceinline__ float tf32r(float x) {
    uint32_t u;
    asm("cvt.rna.tf32.f32 %0, %1;" : "=r"(u) : "f"(x));
    return __uint_as_float(u);
}

__device__ __forceinline__ float ex2(float x) {
    float y;
    asm("ex2.approx.ftz.f32 %0, %1;" : "=f"(y) : "f"(x));
    return y;
}

// D(f32) += A(tf32) * B(tf32), m16n8k8
__device__ __forceinline__ void mma_tf32(float* d,
                                         uint32_t a0, uint32_t a1,
                                         uint32_t a2, uint32_t a3,
                                         uint32_t b0, uint32_t b1) {
    asm volatile(
        "mma.sync.aligned.m16n8k8.row.col.f32.tf32.tf32.f32 "
        "{%0,%1,%2,%3}, {%4,%5,%6,%7}, {%8,%9}, {%0,%1,%2,%3};\n"
        : "+f"(d[0]), "+f"(d[1]), "+f"(d[2]), "+f"(d[3])
        : "r"(a0), "r"(a1), "r"(a2), "r"(a3), "r"(b0), "r"(b1));
}

// ---------------------------------------------------------------------------
// Elementwise tf32 rounding. which: 0 -> g_xr, 1 -> g_wqkvr, 2 -> g_woutr
// ---------------------------------------------------------------------------
__global__ void round_tf32_kernel(const float* __restrict__ in, int n4, int which)
{
    float* out = (which == 0) ? g_xr : (which == 1) ? g_wqkvr : g_woutr;
    int i = blockIdx.x * blockDim.x + threadIdx.x;
    if (i < n4) {
        float4 v = ((const float4*)in)[i];
        v.x = tf32r(v.x); v.y = tf32r(v.y);
        v.z = tf32r(v.z); v.w = tf32r(v.w);
        ((float4*)out)[i] = v;
    }
}

// ---------------------------------------------------------------------------
// tf32 mma.sync GEMM:  C[M,N] = X[M,1024] @ W[1024,N] (+bias)
// CTA tile 128x128, BK=32, 128 threads = 4 warps (2m x 2n), warp tile 64x64.
// 1.0 scalar-LDS per MMA; double-buffered smem via cp.async.
// mode 0: X=g_xr, W=g_wqkvr, scatter epilogue into g_q(*0.125)/g_k/g_v (tf32r)
// mode 1: X=g_ao, W=g_woutr, plain epilogue (+bias) into Cout
// ---------------------------------------------------------------------------
#define GS_XSTRIDE 36            // floats per A-row (32 + 4 pad)  -> bank 4r+q
#define GS_WSTRIDE 136           // floats per B-row (128 + 8 pad) -> bank 8q+r
#define GS_XSTAGE  (128 * GS_XSTRIDE)   // 4608 floats
#define GS_WSTAGE  (32 * GS_WSTRIDE)    // 4352 floats
#define GS_WBASE   (2 * GS_XSTAGE)      // 9216 floats
#define GEMM_SMEM  ((2 * GS_XSTAGE + 2 * GS_WSTAGE) * 4)   // 71680 B

__global__ __launch_bounds__(128, 2) void mma_gemm_kernel(
    const float* __restrict__ bias, float* __restrict__ Cout,
    int N, int mode)
{
    extern __shared__ float sm[];
    const uint32_t sb = smem_u32(sm);
    const int tid = threadIdx.x, lane = tid & 31, w = tid >> 5;
    const int m0 = blockIdx.y * 128, n0 = blockIdx.x * 128;
    const int wm = (w >> 1) * 64, wn = (w & 1) * 64;
    const int q = lane & 3, r = lane >> 2;

    const float* X = (mode == 0) ? g_xr : g_ao;
    const float* W = (mode == 0) ? g_wqkvr : g_woutr;

    float c[4][8][4];
    #pragma unroll
    for (int mt = 0; mt < 4; mt++)
        #pragma unroll
        for (int nt = 0; nt < 8; nt++)
            #pragma unroll
            for (int k = 0; k < 4; k++) c[mt][nt][k] = 0.f;

    auto load_stage = [&](int s, int kt) {
        const int k0 = kt * 32;
        const uint32_t xb = sb + (uint32_t)(s * GS_XSTAGE) * 4;
        const uint32_t wb = sb + (uint32_t)(GS_WBASE + s * GS_WSTAGE) * 4;
        #pragma unroll
        for (int i = 0; i < 8; i++) {
            const int idx = tid + i * 128;
            const int row = idx >> 3, kc = (idx & 7) * 4;
            cp_async16(xb + (uint32_t)(row * GS_XSTRIDE + kc) * 4,
                       X + (size_t)(m0 + row) * DMODEL + k0 + kc);
        }
        #pragma unroll
        for (int i = 0; i < 8; i++) {
            const int idx = tid + i * 128;
            const int row = idx >> 5, nc = (idx & 31) * 4;
            cp_async16(wb + (uint32_t)(row * GS_WSTRIDE + nc) * 4,
                       W + (size_t)(k0 + row) * N + n0 + nc);
        }
    };

    load_stage(0, 0);
    CP_COMMIT();

    const int NT = DMODEL / 32;   // 32 k-stages
    for (int kt = 0; kt < NT; kt++) {
        if (kt + 1 < NT) { load_stage((kt + 1) & 1, kt + 1); CP_COMMIT(); }
        if (kt + 1 < NT) CP_WAIT(1); else CP_WAIT(0);
        __syncthreads();

        const float* xs = sm + (kt & 1) * GS_XSTAGE;
        const float* ws = sm + GS_WBASE + (kt & 1) * GS_WSTAGE;

        #pragma unroll
        for (int ks = 0; ks < 4; ks++) {
            uint32_t a[4][4];
            #pragma unroll
            for (int mt = 0; mt < 4; mt++) {
                const int row = wm + mt * 16 + r;
                a[mt][0] = __float_as_uint(xs[row * GS_XSTRIDE + ks * 8 + q]);
                a[mt][1] = __float_as_uint(xs[(row + 8) * GS_XSTRIDE + ks * 8 + q]);
                a[mt][2] = __float_as_uint(xs[row * GS_XSTRIDE + ks * 8 + q + 4]);
                a[mt][3] = __float_as_uint(xs[(row + 8) * GS_XSTRIDE + ks * 8 + q + 4]);
            }
            #pragma unroll
            for (int nt = 0; nt < 8; nt++) {
                const int col = wn + nt * 8 + r;
                const uint32_t b0 = __float_as_uint(ws[(ks * 8 + q) * GS_WSTRIDE + col]);
                const uint32_t b1 = __float_as_uint(ws[(ks * 8 + q + 4) * GS_WSTRIDE + col]);
                #pragma unroll
                for (int mt = 0; mt < 4; mt++)
                    mma_tf32(c[mt][nt], a[mt][0], a[mt][1], a[mt][2], a[mt][3], b0, b1);
            }
        }
        __syncthreads();
    }

    // Epilogue
    #pragma unroll
    for (int mt = 0; mt < 4; mt++) {
        #pragma unroll
        for (int half = 0; half < 2; half++) {
            const int m = m0 + wm + mt * 16 + r + half * 8;
            #pragma unroll
            for (int nt = 0; nt < 8; nt++) {
                const int n = n0 + wn + nt * 8 + 2 * q;
                float v0 = c[mt][nt][half * 2 + 0] + bias[n];
                float v1 = c[mt][nt][half * 2 + 1] + bias[n + 1];
                if (mode == 0) {
                    const int sec = n >> 10, dcol = n & 1023;
                    const int h = dcol >> 6, dh = dcol & 63;
                    const int b_ = m >> 11, s_ = m & 2047;
                    float* dst;
                    if (sec == 0) { v0 *= 0.125f; v1 *= 0.125f; dst = g_q; }
                    else dst = (sec == 1) ? g_k : g_v;
                    const int bh = b_ * NHEAD + h;
                    *(float2*)&dst[((size_t)bh * SEQ + s_) * DHEAD + dh] =
                        make_float2(tf32r(v0), tf32r(v1));
                } else {
                    *(float2*)&Cout[(size_t)m * DMODEL + n] = make_float2(v0, v1);
                }
            }
        }
    }
}

// ---------------------------------------------------------------------------
// Flash attention on tf32 mma.sync.
// CTA = 256 Q rows of one (b,h); 256 threads = 8 warps; warp w owns rows
// [w*32, w*32+32) (2 m16 tiles). Per key-tile (64 keys): S = Q@K^T (mma),
// fragment online softmax in exp2 domain, P per-warp through smem, O += P@V.
// K/V double-buffered via cp.async. Strides: Q/K/P 68 (bank 4r+q on frag
// loads), V 72 (bank 8q+r on PV B-frag loads).
// smem floats: Q[256][68] @0 | K[2][64][68] @17408 | V[2][64][72] @26112
//              | P[256][68] @35328   total 52736 floats = 210944 B
// ---------------------------------------------------------------------------
#define AQ_STRIDE 68
#define AK_STRIDE 68
#define AV_STRIDE 72
#define AP_STRIDE 68
#define A_KOFF  17408
#define A_KTILE (64 * AK_STRIDE)     // 4352
#define A_VOFF  26112
#define A_VTILE (64 * AV_STRIDE)     // 4608
#define A_POFF  35328
#define ATTN_SMEM (52736 * 4)        // 210944 B

__global__ __launch_bounds__(256, 1) void attn_mma_kernel()
{
    extern __shared__ float sm[];
    const uint32_t sb = smem_u32(sm);
    const int bh = blockIdx.y, q0 = blockIdx.x * 256;
    const int tid = threadIdx.x, lane = tid & 31, w = tid >> 5;
    const int q = lane & 3, r = lane >> 2;
    const int wr0 = w * 32;

    const float* qg = g_q + ((size_t)bh * SEQ + q0) * DHEAD;
    const float* kg = g_k + (size_t)bh * SEQ * DHEAD;
    const float* vg = g_v + (size_t)bh * SEQ * DHEAD;

    auto load_kv = [&](int s, int kc0) {
        #pragma unroll
        for (int i = 0; i < 4; i++) {
            const int idx = tid + i * 256;
            const int row = idx >> 4, c4 = (idx & 15) * 4;
            cp_async16(sb + (uint32_t)(A_KOFF + s * A_KTILE + row * AK_STRIDE + c4) * 4,
                       kg + (size_t)(kc0 + row) * DHEAD + c4);
            cp_async16(sb + (uint32_t)(A_VOFF + s * A_VTILE + row * AV_STRIDE + c4) * 4,
                       vg + (size_t)(kc0 + row) * DHEAD + c4);
        }
    };

    load_kv(0, 0);
    CP_COMMIT();

    // Q tile (256 rows; already scaled by 1/8 and tf32-rounded)
    #pragma unroll
    for (int i = 0; i < 16; i++) {
        const int idx = tid + i * 256;
        const int row = idx >> 4, c4 = (idx & 15) * 4;
        *(float4*)&sm[row * AQ_STRIDE + c4] = *(const float4*)(qg + (size_t)row * DHEAD + c4);
    }

    float mx[2][2], l[2][2];
    float oacc[2][8][4];
    #pragma unroll
    for (int mt = 0; mt < 2; mt++) {
        mx[mt][0] = -INFINITY; mx[mt][1] = -INFINITY;
        l[mt][0] = 0.f; l[mt][1] = 0.f;
        #pragma unroll
        for (int nt = 0; nt < 8; nt++)
            #pragma unroll
            for (int k = 0; k < 4; k++) oacc[mt][nt][k] = 0.f;
    }

    float* Ps = sm + A_POFF;

    for (int kt = 0; kt < 32; kt++) {
        const int buf = kt & 1;
        if (kt + 1 < 32) { load_kv((kt + 1) & 1, (kt + 1) * 64); CP_COMMIT(); }
        if (kt + 1 < 32) CP_WAIT(1); else CP_WAIT(0);
        __syncthreads();

        const float* ks = sm + A_KOFF + buf * A_KTILE;
        const float* vs = sm + A_VOFF + buf * A_VTILE;

        // S = Q @ K^T  (warp: 32 rows x 64 keys)
        float sacc[2][8][4];
        #pragma unroll
        for (int mt = 0; mt < 2; mt++)
            #pragma unroll
            for (int nt = 0; nt < 8; nt++)
                #pragma unroll
                for (int k = 0; k < 4; k++) sacc[mt][nt][k] = 0.f;

        #pragma unroll
        for (int ksi = 0; ksi < 8; ksi++) {
            uint32_t a[2][4];
            #pragma unroll
            for (int mt = 0; mt < 2; mt++) {
                const int row = wr0 + mt * 16 + r;
                a[mt][0] = __float_as_uint(sm[row * AQ_STRIDE + ksi * 8 + q]);
                a[mt][1] = __float_as_uint(sm[(row + 8) * AQ_STRIDE + ksi * 8 + q]);
                a[mt][2] = __float_as_uint(sm[row * AQ_STRIDE + ksi * 8 + q + 4]);
                a[mt][3] = __float_as_uint(sm[(row + 8) * AQ_STRIDE + ksi * 8 + q + 4]);
            }
            #pragma unroll
            for (int nt = 0; nt < 8; nt++) {
                const uint32_t b0 = __float_as_uint(ks[(nt * 8 + r) * AK_STRIDE + ksi * 8 + q]);
                const uint32_t b1 = __float_as_uint(ks[(nt * 8 + r) * AK_STRIDE + ksi * 8 + q + 4]);
                mma_tf32(sacc[0][nt], a[0][0], a[0][1], a[0][2], a[0][3], b0, b1);
                mma_tf32(sacc[1][nt], a[1][0], a[1][1], a[1][2], a[1][3], b0, b1);
            }
        }

        // Online softmax in exp2 domain (Q pre-scaled, so logit = S)
        const float L2E = 1.4426950408889634f;
        #pragma unroll
        for (int mt = 0; mt < 2; mt++) {
            float tmax0 = -INFINITY, tmax1 = -INFINITY;
            #pragma unroll
            for (int nt = 0; nt < 8; nt++) {
                #pragma unroll
                for (int k = 0; k < 4; k++) sacc[mt][nt][k] *= L2E;
                tmax0 = fmaxf(tmax0, fmaxf(sacc[mt][nt][0], sacc[mt][nt][1]));
                tmax1 = fmaxf(tmax1, fmaxf(sacc[mt][nt][2], sacc[mt][nt][3]));
            }
            #pragma unroll
            for (int o = 1; o < 4; o <<= 1) {
                tmax0 = fmaxf(tmax0, __shfl_xor_sync(0xffffffffu, tmax0, o));
                tmax1 = fmaxf(tmax1, __shfl_xor_sync(0xffffffffu, tmax1, o));
            }
            const float mn0 = fmaxf(mx[mt][0], tmax0), mn1 = fmaxf(mx[mt][1], tmax1);
            const float f0 = ex2(mx[mt][0] - mn0),     f1 = ex2(mx[mt][1] - mn1);
            float rs0 = 0.f, rs1 = 0.f;
            #pragma unroll
            for (int nt = 0; nt < 8; nt++) {
                sacc[mt][nt][0] = ex2(sacc[mt][nt][0] - mn0);
                sacc[mt][nt][1] = ex2(sacc[mt][nt][1] - mn0);
                sacc[mt][nt][2] = ex2(sacc[mt][nt][2] - mn1);
                sacc[mt][nt][3] = ex2(sacc[mt][nt][3] - mn1);
                rs0 += sacc[mt][nt][0] + sacc[mt][nt][1];
                rs1 += sacc[mt][nt][2] + sacc[mt][nt][3];
            }
            #pragma unroll
            for (int o = 1; o < 4; o <<= 1) {
                rs0 += __shfl_xor_sync(0xffffffffu, rs0, o);
                rs1 += __shfl_xor_sync(0xffffffffu, rs1, o);
            }
            l[mt][0] = l[mt][0] * f0 + rs0;  l[mt][1] = l[mt][1] * f1 + rs1;
            mx[mt][0] = mn0;                 mx[mt][1] = mn1;

            // Rescale O, stage P (warp-private rows: __syncwarp is sufficient)
            const int prow = wr0 + mt * 16 + r;
            #pragma unroll
            for (int nt = 0; nt < 8; nt++) {
                oacc[mt][nt][0] *= f0; oacc[mt][nt][1] *= f0;
                oacc[mt][nt][2] *= f1; oacc[mt][nt][3] *= f1;
                *(float2*)&Ps[prow * AP_STRIDE + nt * 8 + 2 * q] =
                    make_float2(tf32r(sacc[mt][nt][0]), tf32r(sacc[mt][nt][1]));
                *(float2*)&Ps[(prow + 8) * AP_STRIDE + nt * 8 + 2 * q] =
                    make_float2(tf32r(sacc[mt][nt][2]), tf32r(sacc[mt][nt][3]));
            }
        }
        __syncwarp();

        // O += P @ V
        #pragma unroll
        for (int ksi = 0; ksi < 8; ksi++) {
            uint32_t a[2][4];
            #pragma unroll
            for (int mt = 0; mt < 2; mt++) {
                const int row = wr0 + mt * 16 + r;
                a[mt][0] = __float_as_uint(Ps[row * AP_STRIDE + ksi * 8 + q]);
                a[mt][1] = __float_as_uint(Ps[(row + 8) * AP_STRIDE + ksi * 8 + q]);
                a[mt][2] = __float_as_uint(Ps[row * AP_STRIDE + ksi * 8 + q + 4]);
                a[mt][3] = __float_as_uint(Ps[(row + 8) * AP_STRIDE + ksi * 8 + q + 4]);
            }
            #pragma unroll
            for (int nt = 0; nt < 8; nt++) {
                const uint32_t b0 = __float_as_uint(vs[(ksi * 8 + q) * AV_STRIDE + nt * 8 + r]);
                const uint32_t b1 = __float_as_uint(vs[(ksi * 8 + q + 4) * AV_STRIDE + nt * 8 + r]);
                mma_tf32(oacc[0][nt], a[0][0], a[0][1], a[0][2], a[0][3], b0, b1);
                mma_tf32(oacc[1][nt], a[1][0], a[1][1], a[1][2], a[1][3], b0, b1);
            }
        }
        __syncthreads();   // all reads of K/V[buf] done before next prefetch overwrites
    }

    // Epilogue: normalize, round to tf32 (g_ao feeds the out-proj mma GEMM)
    const int b_ = bh >> 4, h = bh & (NHEAD - 1);
    #pragma unroll
    for (int mt = 0; mt < 2; mt++) {
        const float inv0 = 1.f / l[mt][0], inv1 = 1.f / l[mt][1];
        const size_t base0 =
            ((size_t)(b_ * SEQ + q0 + wr0 + mt * 16 + r)) * DMODEL + h * DHEAD;
        const size_t base1 = base0 + (size_t)8 * DMODEL;
        #pragma unroll
        for (int nt = 0; nt < 8; nt++) {
            *(float2*)&g_ao[base0 + nt * 8 + 2 * q] =
                make_float2(tf32r(oacc[mt][nt][0] * inv0), tf32r(oacc[mt][nt][1] * inv0));
            *(float2*)&g_ao[base1 + nt * 8 + 2 * q] =
                make_float2(tf32r(oacc[mt][nt][2] * inv1), tf32r(oacc[mt][nt][3] * inv1));
        }
    }
}

// ---------------------------------------------------------------------------
extern "C" void kernel_launch(void* const* d_in, const int* in_sizes, int n_in,
                              void* d_out, int out_size)
{
    const float* x     = (const float*)d_in[0];
    const float* w_qkv = (const float*)d_in[1];
    const float* b_qkv = (const float*)d_in[2];
    const float* w_out = (const float*)d_in[3];
    const float* b_out = (const float*)d_in[4];
    float* out = (float*)d_out;

    cudaFuncSetAttribute(mma_gemm_kernel,
                         cudaFuncAttributeMaxDynamicSharedMemorySize, GEMM_SMEM);
    cudaFuncSetAttribute(attn_mma_kernel,
                         cudaFuncAttributeMaxDynamicSharedMemorySize, ATTN_SMEM);

    // Round inputs to tf32 (destinations selected inside the kernel)
    round_tf32_kernel<<<(MROWS * DMODEL / 4 + 255) / 256, 256>>>(x, MROWS * DMODEL / 4, 0);
    round_tf32_kernel<<<(DMODEL * NQKV / 4 + 255) / 256, 256>>>(w_qkv, DMODEL * NQKV / 4, 1);
    round_tf32_kernel<<<(DMODEL * DMODEL / 4 + 255) / 256, 256>>>(w_out, DMODEL * DMODEL / 4, 2);

    // QKV projection
    dim3 g1(NQKV / 128, MROWS / 128);   // 24 x 64
    mma_gemm_kernel<<<g1, 128, GEMM_SMEM>>>(b_qkv, nullptr, NQKV, 0);

    // Attention
    dim3 g2(SEQ / 256, BATCH * NHEAD);  // 8 x 64
    attn_mma_kernel<<<g2, 256, ATTN_SMEM>>>();

    // Output projection
    dim3 g3(DMODEL / 128, MROWS / 128); // 8 x 64
    mma_gemm_kernel<<<g3, 128, GEMM_SMEM>>>(b_out, out, DMODEL, 1);
}